// round 5
// baseline (speedup 1.0000x reference)
#include <cuda_runtime.h>
#include <cuda_bf16.h>
#include <cstdint>

#define NGRAPH 8192
#define NP 32
#define HDIM 128
#define NEDGE 524288
#define NNODE (NGRAPH * NP)

typedef __nv_bfloat16 bf16;

// ================= static device scratch =================
__device__ __align__(16) int  g_adj[NGRAPH * 1024];
__device__ __align__(16) bf16 g_featH[(size_t)NNODE * 128];
__device__ __align__(16) bf16 g_featL[(size_t)NNODE * 128];
__device__ __align__(16) bf16 g_AggH[(size_t)NNODE * 256];
__device__ __align__(16) bf16 g_AggL[(size_t)NNODE * 256];
__device__ __align__(16) bf16 g_HNh[(size_t)NNODE * 128];
__device__ __align__(16) bf16 g_HNl[(size_t)NNODE * 128];
__device__ __align__(16) float g_FV[(size_t)NGRAPH * 128];
__device__ __align__(16) bf16 g_WioH[256 * 128], g_WioL[256 * 128];
__device__ __align__(16) bf16 g_WgH[512 * 384], g_WgL[512 * 384];
__device__ __align__(16) bf16 g_WuH[128 * 128], g_WuL[128 * 128];
__device__ __align__(16) bf16 g_WvH[128 * 128], g_WvL[128 * 128];
__device__ __align__(16) float g_biasY[256];
__device__ __align__(16) float g_biasG[512];

// gates schedule: (gate block nb, K chunk) pairs. nb3 last (feat in stages).
__constant__ int c_snb[18] = {0,0,0,0,0,0, 1,1,1,1,1,1, 2,2,2,2, 3,3};
__constant__ int c_skc[18] = {0,64,128,192,256,320, 0,64,128,192,256,320,
                              0,64,128,192, 256,320};

// ================= helpers =================
__device__ __forceinline__ uint32_t smem_to_u32(const void* p) {
  uint32_t a;
  asm("{ .reg .u64 tmp; cvta.to.shared.u64 tmp, %1; cvt.u32.u64 %0, tmp; }"
      : "=r"(a) : "l"(p));
  return a;
}
#define SWZ(off) ((off) ^ (((off) >> 3) & 0x70))

__device__ __forceinline__ void cp16(uint32_t dst, const void* src) {
  asm volatile("cp.async.cg.shared.global [%0], [%1], 16;" ::"r"(dst), "l"(src));
}
#define CP_COMMIT() asm volatile("cp.async.commit_group;" ::: "memory")
#define CP_WAIT(n) asm volatile("cp.async.wait_group %0;" ::"n"(n) : "memory")

__device__ __forceinline__ void ldsm_x4(uint32_t addr, uint32_t* r) {
  asm volatile("ldmatrix.sync.aligned.m8n8.x4.shared.b16 {%0,%1,%2,%3}, [%4];"
               : "=r"(r[0]), "=r"(r[1]), "=r"(r[2]), "=r"(r[3]) : "r"(addr));
}
__device__ __forceinline__ void mma16816(float* d, const uint32_t* a,
                                         const uint32_t* b) {
  asm volatile(
      "mma.sync.aligned.m16n8k16.row.col.f32.bf16.bf16.f32 "
      "{%0,%1,%2,%3}, {%4,%5,%6,%7}, {%8,%9}, {%0,%1,%2,%3};"
      : "+f"(d[0]), "+f"(d[1]), "+f"(d[2]), "+f"(d[3])
      : "r"(a[0]), "r"(a[1]), "r"(a[2]), "r"(a[3]), "r"(b[0]), "r"(b[1]));
}

__device__ __forceinline__ float sigf(float x) { return 1.f / (1.f + __expf(-x)); }
__device__ __forceinline__ float tanh_fast(float x) {
  float e2x = __expf(2.f * x);
  return 1.f - 2.f / (e2x + 1.f);
}
__device__ __forceinline__ void split2(float v, bf16* h, bf16* l) {
  bf16 hi = __float2bfloat16(v);
  *h = hi;
  *l = __float2bfloat16(v - __bfloat162float(hi));
}
__device__ __forceinline__ float b2f(bf16 v) { return __bfloat162float(v); }
__device__ __forceinline__ uint32_t packbf(bf16 a, bf16 b) {
  return (uint32_t)__bfloat16_as_ushort(a) |
         ((uint32_t)__bfloat16_as_ushort(b) << 16);
}

// ================= adjacency =================
__global__ void k_zero_adj() {
  int i = blockIdx.x * blockDim.x + threadIdx.x;
  int stride = gridDim.x * blockDim.x;
  int4* p = (int4*)g_adj;
  const int n4 = NGRAPH * 1024 / 4;
  int4 z = make_int4(0, 0, 0, 0);
  for (; i < n4; i += stride) p[i] = z;
}
__global__ void k_build_adj(const int* __restrict__ src, const int* __restrict__ dst) {
  int e = blockIdx.x * blockDim.x + threadIdx.x;
  if (e >= NEDGE) return;
  int d = dst[e];
  int s = src[e];
  atomicAdd(&g_adj[((d >> 5) << 10) + ((d & 31) << 5) + (s & 31)], 1);
}

// ================= weight pack + split =================
__global__ void k_pack(const float* __restrict__ W_in, const float* __restrict__ W_og,
                       const float* __restrict__ W_ih, const float* __restrict__ W_hh,
                       const float* __restrict__ W_u, const float* __restrict__ W_v,
                       const float* __restrict__ b_in, const float* __restrict__ b_og,
                       const float* __restrict__ b_ih, const float* __restrict__ b_hh) {
  int i0 = blockIdx.x * 256 + threadIdx.x;
  int stride = gridDim.x * 256;
  for (int i = i0; i < 256 * 128; i += stride) {
    int r = i >> 7, c = i & 127;
    float v = (r < 128) ? W_in[r * 128 + c] : W_og[(r - 128) * 128 + c];
    split2(v, &g_WioH[i], &g_WioL[i]);
  }
  for (int i = i0; i < 512 * 384; i += stride) {
    int r = i / 384, c = i % 384;
    int blk = r >> 7, rr = r & 127;
    float v;
    if (blk == 0)      v = (c < 256) ? W_ih[rr * 256 + c] : W_hh[rr * 128 + (c - 256)];
    else if (blk == 1) v = (c < 256) ? W_ih[(128 + rr) * 256 + c] : W_hh[(128 + rr) * 128 + (c - 256)];
    else if (blk == 2) v = (c < 256) ? W_ih[(256 + rr) * 256 + c] : 0.f;
    else               v = (c < 256) ? 0.f : W_hh[(256 + rr) * 128 + (c - 256)];
    split2(v, &g_WgH[i], &g_WgL[i]);
  }
  for (int i = i0; i < 128 * 128; i += stride) {
    split2(W_u[i], &g_WuH[i], &g_WuL[i]);
    split2(W_v[i], &g_WvH[i], &g_WvL[i]);
  }
  for (int i = i0; i < 256; i += stride)
    g_biasY[i] = (i < 128) ? b_in[i] : b_og[i - 128];
  for (int i = i0; i < 512; i += stride) {
    float v;
    if (i < 256)      v = b_ih[i] + b_hh[i];
    else if (i < 384) v = b_ih[i];
    else              v = b_hh[i - 128];
    g_biasG[i] = v;
  }
}

__global__ void k_split_feat(const float* __restrict__ feat) {
  size_t i = (size_t)blockIdx.x * 256 + threadIdx.x;
  size_t stride = (size_t)gridDim.x * 256;
  const size_t n = (size_t)NNODE * 128;
  for (; i < n; i += stride) split2(feat[i], &g_featH[i], &g_featL[i]);
}

// ================= generic 128x128 GEMM (PLAIN / AGG epilogue) =================
#define EPI_PLAIN 0
#define EPI_AGG 1

#define SG 65536
#define T_AH 0
#define T_AL 16384
#define T_BH 32768
#define T_BL 49152

template <int EPI>
__global__ void __launch_bounds__(256, 1) k_mma(
    const bf16* __restrict__ A1h, const bf16* __restrict__ A1l, int lda1,
    const bf16* __restrict__ Bh0, const bf16* __restrict__ Bl0, int ldb,
    const float* __restrict__ bias, float* __restrict__ C, int ldc) {
  extern __shared__ __align__(1024) char smem[];
  const uint32_t sb = smem_to_u32(smem);
  const int tid = threadIdx.x;
  const int lid = tid & 31, wid = tid >> 5;
  const int m0 = blockIdx.x * 128;
  const int nb = blockIdx.y;
  const int wm0 = (wid & 3) * 32, wn0 = (wid >> 2) * 64;

  const bf16* Bh = Bh0 + (size_t)nb * 128 * ldb;
  const bf16* Bl = Bl0 + (size_t)nb * 128 * ldb;
  const int nchunks = ldb >> 6;

  auto issue = [&](int kc, int s) {
    uint32_t base = sb + s * SG;
#pragma unroll
    for (int i = 0; i < 4; i++) {
      int u = tid + 256 * i;
      int r = u >> 3, seg = u & 7;
      uint32_t d = SWZ(r * 128 + seg * 16);
      size_t aoff = (size_t)(m0 + r) * lda1 + kc + seg * 8;
      cp16(base + T_AH + d, A1h + aoff);
      cp16(base + T_AL + d, A1l + aoff);
      size_t boff = (size_t)r * ldb + kc + seg * 8;
      cp16(base + T_BH + d, Bh + boff);
      cp16(base + T_BL + d, Bl + boff);
    }
    CP_COMMIT();
  };

  float acc[2][8][4];
#pragma unroll
  for (int mi = 0; mi < 2; mi++)
#pragma unroll
    for (int ni = 0; ni < 8; ni++)
#pragma unroll
      for (int q = 0; q < 4; q++) acc[mi][ni][q] = 0.f;

  issue(0, 0);
  for (int c = 0; c < nchunks; c++) {
    if (c + 1 < nchunks) {
      issue((c + 1) * 64, (c + 1) & 1);
      CP_WAIT(1);
    } else {
      CP_WAIT(0);
    }
    __syncthreads();
    const uint32_t st = sb + (c & 1) * SG;
    const int j = lid >> 3, rr = lid & 7;
#pragma unroll
    for (int kk = 0; kk < 4; kk++) {
      uint32_t ah[2][4], al[2][4], bh[8][2], bl[8][2];
#pragma unroll
      for (int mi = 0; mi < 2; mi++) {
        int row = wm0 + mi * 16 + (j & 1) * 8 + rr;
        int kb = kk * 32 + (j >> 1) * 16;
        uint32_t ad = st + T_AH + SWZ(row * 128 + kb);
        ldsm_x4(ad, ah[mi]);
        ldsm_x4(ad + (T_AL - T_AH), al[mi]);
      }
#pragma unroll
      for (int p = 0; p < 4; p++) {
        int n = wn0 + p * 16 + (j >> 1) * 8 + rr;
        int kb = kk * 32 + (j & 1) * 16;
        uint32_t bd = st + T_BH + SWZ(n * 128 + kb);
        uint32_t t[4];
        ldsm_x4(bd, t);
        bh[2 * p][0] = t[0]; bh[2 * p][1] = t[1];
        bh[2 * p + 1][0] = t[2]; bh[2 * p + 1][1] = t[3];
        ldsm_x4(bd + (T_BL - T_BH), t);
        bl[2 * p][0] = t[0]; bl[2 * p][1] = t[1];
        bl[2 * p + 1][0] = t[2]; bl[2 * p + 1][1] = t[3];
      }
#pragma unroll
      for (int mi = 0; mi < 2; mi++)
#pragma unroll
        for (int ni = 0; ni < 8; ni++) {
          mma16816(acc[mi][ni], ah[mi], bh[ni]);
          mma16816(acc[mi][ni], ah[mi], bl[ni]);
          mma16816(acc[mi][ni], al[mi], bh[ni]);
        }
    }
    __syncthreads();
  }

  const int gp = lid >> 2, tg = lid & 3;

  if (EPI == EPI_PLAIN) {
#pragma unroll
    for (int mi = 0; mi < 2; mi++)
#pragma unroll
      for (int ni = 0; ni < 8; ni++) {
        int r0 = m0 + wm0 + mi * 16 + gp;
        int c = wn0 + ni * 8 + tg * 2;
        float b0 = bias ? bias[c] : 0.f;
        float b1 = bias ? bias[c + 1] : 0.f;
        *(float2*)&C[(size_t)r0 * ldc + c] =
            make_float2(acc[mi][ni][0] + b0, acc[mi][ni][1] + b1);
        *(float2*)&C[(size_t)(r0 + 8) * ldc + c] =
            make_float2(acc[mi][ni][2] + b0, acc[mi][ni][3] + b1);
      }
  } else {  // EPI_AGG
    float* sC = (float*)smem;  // [128][132]
#pragma unroll
    for (int mi = 0; mi < 2; mi++)
#pragma unroll
      for (int ni = 0; ni < 8; ni++) {
        int r = wm0 + mi * 16 + gp;
        int c = wn0 + ni * 8 + tg * 2;
        float b0 = bias[nb * 128 + c], b1 = bias[nb * 128 + c + 1];
        sC[r * 132 + c] = acc[mi][ni][0] + b0;
        sC[r * 132 + c + 1] = acc[mi][ni][1] + b1;
        sC[(r + 8) * 132 + c] = acc[mi][ni][2] + b0;
        sC[(r + 8) * 132 + c + 1] = acc[mi][ni][3] + b1;
      }
    float* adjf = (float*)(smem + 67584);
    float* rdeg = (float*)(smem + 67584 + 16896);
    const int g0 = m0 >> 5;
    for (int i = tid; i < 4096; i += 256) {
      int gl = i >> 10, rem = i & 1023;
      adjf[gl * 1056 + (rem >> 5) * 33 + (rem & 31)] =
          (float)g_adj[((g0 + gl) << 10) + rem];
    }
    __syncthreads();
    if (tid < 128) {
      int gl = tid >> 5, n = tid & 31;
      float s = 0.f;
#pragma unroll
      for (int k = 0; k < 32; k++)
        s += (nb == 0) ? adjf[gl * 1056 + n * 33 + k]
                       : adjf[gl * 1056 + k * 33 + n];
      rdeg[tid] = 1.f / fmaxf(s, 1.f);
    }
    __syncthreads();
    const int gl = tid >> 6, jj = tid & 63;
    float accA[32], accB[32];
#pragma unroll
    for (int n = 0; n < 32; n++) { accA[n] = 0.f; accB[n] = 0.f; }
    for (int k = 0; k < 32; k++) {
      float c0 = sC[(gl * 32 + k) * 132 + jj];
      float c1 = sC[(gl * 32 + k) * 132 + jj + 64];
#pragma unroll
      for (int n = 0; n < 32; n++) {
        float w = (nb == 0) ? adjf[gl * 1056 + n * 33 + k]
                            : adjf[gl * 1056 + k * 33 + n];
        accA[n] += w * c0;
        accB[n] += w * c1;
      }
    }
#pragma unroll
    for (int n = 0; n < 32; n++) {
      float rd = rdeg[gl * 32 + n];
      float v0 = accA[n] * rd, v1 = accB[n] * rd;
      size_t o = (size_t)(m0 + gl * 32 + n) * 256 + nb * 128;
      split2(v0, &g_AggH[o + jj], &g_AggL[o + jj]);
      split2(v1, &g_AggH[o + jj + 64], &g_AggL[o + jj + 64]);
    }
  }
}

// ================= gates GEMM + fused GRU =================
// BM=64, 4 gate blocks (N=128 each) via static schedule; GRU in epilogue.
#define GSG 49152
#define G_AH 0
#define G_AL 8192
#define G_BH 16384
#define G_BL 32768

#define GMMAS(acc) \
  do { \
    _Pragma("unroll") for (int mi = 0; mi < 2; mi++) \
        _Pragma("unroll") for (int ni = 0; ni < 4; ni++) { \
      mma16816(acc[mi][ni], ah[mi], bh[ni]); \
      mma16816(acc[mi][ni], ah[mi], bl[ni]); \
      mma16816(acc[mi][ni], al[mi], bh[ni]); \
    } \
  } while (0)

__global__ void __launch_bounds__(256, 1) k_gates() {
  extern __shared__ __align__(1024) char smem[];
  const uint32_t sb = smem_to_u32(smem);
  float* sbias = (float*)(smem + 2 * GSG);
  const int tid = threadIdx.x;
  const int lid = tid & 31, wid = tid >> 5;
  const int m0 = blockIdx.x * 64;
  const int wm0 = (wid & 1) * 32, wn0 = (wid >> 1) * 32;

  for (int i = tid; i < 512; i += 256) sbias[i] = g_biasG[i];

  auto issue = [&](int i) {
    int nb = c_snb[i], kc = c_skc[i];
    uint32_t base = sb + (i & 1) * GSG;
    const bf16 *ah, *al;
    int ld, kk;
    if (kc < 256) { ah = g_AggH; al = g_AggL; ld = 256; kk = kc; }
    else { ah = g_featH; al = g_featL; ld = 128; kk = kc - 256; }
#pragma unroll
    for (int u2 = 0; u2 < 2; u2++) {
      int u = tid + 256 * u2;
      int r = u >> 3, seg = u & 7;
      uint32_t d = SWZ(r * 128 + seg * 16);
      size_t aoff = (size_t)(m0 + r) * ld + kk + seg * 8;
      cp16(base + G_AH + d, ah + aoff);
      cp16(base + G_AL + d, al + aoff);
    }
    const bf16* bhp = g_WgH + (size_t)nb * 128 * 384;
    const bf16* blp = g_WgL + (size_t)nb * 128 * 384;
#pragma unroll
    for (int u2 = 0; u2 < 4; u2++) {
      int u = tid + 256 * u2;
      int r = u >> 3, seg = u & 7;
      uint32_t d = SWZ(r * 128 + seg * 16);
      size_t boff = (size_t)r * 384 + kc + seg * 8;
      cp16(base + G_BH + d, bhp + boff);
      cp16(base + G_BL + d, blp + boff);
    }
    CP_COMMIT();
  };

  float accR[2][4][4], accZ[2][4][4], accN[2][4][4], accH[2][4][4];
#pragma unroll
  for (int mi = 0; mi < 2; mi++)
#pragma unroll
    for (int ni = 0; ni < 4; ni++)
#pragma unroll
      for (int q = 0; q < 4; q++) {
        accR[mi][ni][q] = 0.f; accZ[mi][ni][q] = 0.f;
        accN[mi][ni][q] = 0.f; accH[mi][ni][q] = 0.f;
      }

  issue(0);
  for (int i = 0; i < 18; i++) {
    if (i + 1 < 18) { issue(i + 1); CP_WAIT(1); }
    else CP_WAIT(0);
    __syncthreads();
    const uint32_t st = sb + (i & 1) * GSG;
    const int nb = c_snb[i];
    const int j = lid >> 3, rr = lid & 7;
#pragma unroll
    for (int kk = 0; kk < 4; kk++) {
      uint32_t ah[2][4], al[2][4], bh[4][2], bl[4][2];
#pragma unroll
      for (int mi = 0; mi < 2; mi++) {
        int row = wm0 + mi * 16 + (j & 1) * 8 + rr;
        int kb = kk * 32 + (j >> 1) * 16;
        uint32_t ad = st + G_AH + SWZ(row * 128 + kb);
        ldsm_x4(ad, ah[mi]);
        ldsm_x4(ad + (G_AL - G_AH), al[mi]);
      }
#pragma unroll
      for (int p = 0; p < 2; p++) {
        int n = wn0 + p * 16 + (j >> 1) * 8 + rr;
        int kb = kk * 32 + (j & 1) * 16;
        uint32_t bd = st + G_BH + SWZ(n * 128 + kb);
        uint32_t t[4];
        ldsm_x4(bd, t);
        bh[2 * p][0] = t[0]; bh[2 * p][1] = t[1];
        bh[2 * p + 1][0] = t[2]; bh[2 * p + 1][1] = t[3];
        ldsm_x4(bd + (G_BL - G_BH), t);
        bl[2 * p][0] = t[0]; bl[2 * p][1] = t[1];
        bl[2 * p + 1][0] = t[2]; bl[2 * p + 1][1] = t[3];
      }
      switch (nb) {
        case 0: GMMAS(accR); break;
        case 1: GMMAS(accZ); break;
        case 2: GMMAS(accN); break;
        default: GMMAS(accH); break;
      }
    }
    __syncthreads();
  }

  // fused GRU epilogue (feat reconstructed from bf16 hi/lo smem stages)
  const int gp = lid >> 2, tg = lid & 3;
#pragma unroll
  for (int mi = 0; mi < 2; mi++)
#pragma unroll
    for (int rh = 0; rh < 2; rh++) {
      int rowl = wm0 + mi * 16 + gp + rh * 8;
      size_t rowg = m0 + rowl;
#pragma unroll
      for (int ni = 0; ni < 4; ni++) {
        int jb = wn0 + ni * 8 + tg * 2;
        bf16 oh[2], ol[2];
#pragma unroll
        for (int c = 0; c < 2; c++) {
          int jx = jb + c;
          int q = rh * 2 + c;
          float r_ = sigf(accR[mi][ni][q] + sbias[jx]);
          float z_ = sigf(accZ[mi][ni][q] + sbias[128 + jx]);
          float hs = accH[mi][ni][q] + sbias[384 + jx];
          float ng = tanh_fast(accN[mi][ni][q] + sbias[256 + jx] + r_ * hs);
          int stg = jx >> 6, col = jx & 63;
          uint32_t off = SWZ(rowl * 128 + col * 2);
          float f = b2f(*(bf16*)(smem + stg * GSG + G_AH + off)) +
                    b2f(*(bf16*)(smem + stg * GSG + G_AL + off));
          float hn = (1.f - z_) * ng + z_ * f;
          split2(hn, &oh[c], &ol[c]);
        }
        *(uint32_t*)&g_HNh[rowg * 128 + jb] = packbf(oh[0], oh[1]);
        *(uint32_t*)&g_HNl[rowg * 128 + jb] = packbf(ol[0], ol[1]);
      }
    }
}

// ================= U GEMM + attention + readout fused =================
__global__ void __launch_bounds__(256, 1) k_alpha(const float* __restrict__ cnt,
                                                  const float* __restrict__ we,
                                                  float* __restrict__ out) {
  extern __shared__ __align__(1024) char smem[];
  const uint32_t sb = smem_to_u32(smem);
  const int tid = threadIdx.x;
  const int lid = tid & 31, wid = tid >> 5;
  const int m0 = blockIdx.x * 128;
  const int g0 = m0 >> 5;
  const int wm0 = (wid & 3) * 32, wn0 = (wid >> 2) * 64;

  float* sFV = (float*)(smem + 2 * SG);
  float* swe = sFV + 512;
  float* scnt = swe + 128;
  float* sPart = scnt + 128;  // [2][128]
  float* sAl = sPart + 256;

  for (int i = tid; i < 512; i += 256)
    sFV[i] = g_FV[(size_t)(g0 + (i >> 7)) * 128 + (i & 127)];
  if (tid < 128) { swe[tid] = we[tid]; scnt[tid] = cnt[m0 + tid]; }

  auto issue = [&](int kc, int s) {
    uint32_t base = sb + s * SG;
#pragma unroll
    for (int i = 0; i < 4; i++) {
      int u = tid + 256 * i;
      int r = u >> 3, seg = u & 7;
      uint32_t d = SWZ(r * 128 + seg * 16);
      size_t aoff = (size_t)(m0 + r) * 128 + kc + seg * 8;
      cp16(base + T_AH + d, g_HNh + aoff);
      cp16(base + T_AL + d, g_HNl + aoff);
      size_t boff = (size_t)r * 128 + kc + seg * 8;
      cp16(base + T_BH + d, g_WuH + boff);
      cp16(base + T_BL + d, g_WuL + boff);
    }
    CP_COMMIT();
  };

  float acc[2][8][4];
#pragma unroll
  for (int mi = 0; mi < 2; mi++)
#pragma unroll
    for (int ni = 0; ni < 8; ni++)
#pragma unroll
      for (int q = 0; q < 4; q++) acc[mi][ni][q] = 0.f;

  issue(0, 0);
  issue(64, 1);
  for (int c = 0; c < 2; c++) {
    if (c == 0) CP_WAIT(1); else CP_WAIT(0);
    __syncthreads();
    const uint32_t st = sb + c * SG;
    const int j = lid >> 3, rr = lid & 7;
#pragma unroll
    for (int kk = 0; kk < 4; kk++) {
      uint32_t ah[2][4], al[2][4], bh[8][2], bl[8][2];
#pragma unroll
      for (int mi = 0; mi < 2; mi++) {
        int row = wm0 + mi * 16 + (j & 1) * 8 + rr;
        int kb = kk * 32 + (j >> 1) * 16;
        uint32_t ad = st + T_AH + SWZ(row * 128 + kb);
        ldsm_x4(ad, ah[mi]);
        ldsm_x4(ad + (T_AL - T_AH), al[mi]);
      }
#pragma unroll
      for (int p = 0; p < 4; p++) {
        int n = wn0 + p * 16 + (j >> 1) * 8 + rr;
        int kb = kk * 32 + (j & 1) * 16;
        uint32_t bd = st + T_BH + SWZ(n * 128 + kb);
        uint32_t t[4];
        ldsm_x4(bd, t);
        bh[2 * p][0] = t[0]; bh[2 * p][1] = t[1];
        bh[2 * p + 1][0] = t[2]; bh[2 * p + 1][1] = t[3];
        ldsm_x4(bd + (T_BL - T_BH), t);
        bl[2 * p][0] = t[0]; bl[2 * p][1] = t[1];
        bl[2 * p + 1][0] = t[2]; bl[2 * p + 1][1] = t[3];
      }
#pragma unroll
      for (int mi = 0; mi < 2; mi++)
#pragma unroll
        for (int ni = 0; ni < 8; ni++) {
          mma16816(acc[mi][ni], ah[mi], bh[ni]);
          mma16816(acc[mi][ni], ah[mi], bl[ni]);
          mma16816(acc[mi][ni], al[mi], bh[ni]);
        }
    }
    __syncthreads();
  }

  // attention: e = sum_j we[j]*sig(U + FV[g][j]); alpha = e*cnt
  const int gp = lid >> 2, tg = lid & 3;
#pragma unroll
  for (int mi = 0; mi < 2; mi++) {
    int base = wm0 + mi * 16;
    int gl = base >> 5;
    float p0 = 0.f, p1 = 0.f;
#pragma unroll
    for (int ni = 0; ni < 8; ni++) {
      int jx = wn0 + ni * 8 + tg * 2;
      float fv0 = sFV[gl * 128 + jx], fv1 = sFV[gl * 128 + jx + 1];
      float w0 = swe[jx], w1 = swe[jx + 1];
      p0 += w0 * sigf(acc[mi][ni][0] + fv0) + w1 * sigf(acc[mi][ni][1] + fv1);
      p1 += w0 * sigf(acc[mi][ni][2] + fv0) + w1 * sigf(acc[mi][ni][3] + fv1);
    }
    p0 += __shfl_xor_sync(0xffffffffu, p0, 1);
    p0 += __shfl_xor_sync(0xffffffffu, p0, 2);
    p1 += __shfl_xor_sync(0xffffffffu, p1, 1);
    p1 += __shfl_xor_sync(0xffffffffu, p1, 2);
    if (tg == 0) {
      sPart[(wid >> 2) * 128 + base + gp] = p0;
      sPart[(wid >> 2) * 128 + base + gp + 8] = p1;
    }
  }
  __syncthreads();
  if (tid < 128)
    sAl[tid] = (sPart[tid] + sPart[128 + tid]) * scnt[tid];
  __syncthreads();

  // readout: hn reconstructed from HN hi/lo tiles still in both smem stages
#pragma unroll
  for (int v = 0; v < 2; v++) {
    int idx = tid + v * 256;
    int gl = idx >> 7, jx = idx & 127;
    int stg = jx >> 6, col = jx & 63;
    float accg = 0.f, hn31 = 0.f;
#pragma unroll
    for (int n = 0; n < 32; n++) {
      int rowl = gl * 32 + n;
      uint32_t off = SWZ(rowl * 128 + col * 2);
      float hn = b2f(*(bf16*)(smem + stg * SG + T_AH + off)) +
                 b2f(*(bf16*)(smem + stg * SG + T_AL + off));
      accg += hn * sAl[rowl];
      if (n == 31) hn31 = hn;
    }
    out[(size_t)(g0 + gl) * 256 + jx] = accg;
    out[(size_t)(g0 + gl) * 256 + 128 + jx] = hn31;
  }
}

// ================= host =================
extern "C" void kernel_launch(void* const* d_in, const int* in_sizes, int n_in,
                              void* d_out, int out_size) {
  const float* feat = (const float*)d_in[0];
  const float* cnt  = (const float*)d_in[1];
  const float* W_in = (const float*)d_in[2];
  const float* b_in = (const float*)d_in[3];
  const float* W_og = (const float*)d_in[4];
  const float* b_og = (const float*)d_in[5];
  const float* W_ih = (const float*)d_in[6];
  const float* b_ih = (const float*)d_in[7];
  const float* W_hh = (const float*)d_in[8];
  const float* b_hh = (const float*)d_in[9];
  const float* W_u  = (const float*)d_in[10];
  const float* W_v  = (const float*)d_in[11];
  const float* b_v  = (const float*)d_in[12];
  const float* w_e  = (const float*)d_in[13];
  const int*   src  = (const int*)d_in[14];
  const int*   dst  = (const int*)d_in[15];
  float* out = (float*)d_out;

  bf16 *featH, *featL, *HNh, *HNl, *WioH, *WioL, *WvH, *WvL;
  float *FV, *biasY;
  cudaGetSymbolAddress((void**)&featH, g_featH);
  cudaGetSymbolAddress((void**)&featL, g_featL);
  cudaGetSymbolAddress((void**)&HNh, g_HNh);
  cudaGetSymbolAddress((void**)&HNl, g_HNl);
  cudaGetSymbolAddress((void**)&FV, g_FV);
  cudaGetSymbolAddress((void**)&WioH, g_WioH);
  cudaGetSymbolAddress((void**)&WioL, g_WioL);
  cudaGetSymbolAddress((void**)&WvH, g_WvH);
  cudaGetSymbolAddress((void**)&WvL, g_WvL);
  cudaGetSymbolAddress((void**)&biasY, g_biasY);

  const int SM_MMA = 131072;
  const int SM_GATES = 2 * GSG + 2048;          // 100352
  const int SM_ALPHA = 131072 + 4608;           // 135680
  static bool attr_done = false;
  if (!attr_done) {
    cudaFuncSetAttribute(k_mma<EPI_PLAIN>, cudaFuncAttributeMaxDynamicSharedMemorySize, SM_MMA);
    cudaFuncSetAttribute(k_mma<EPI_AGG>, cudaFuncAttributeMaxDynamicSharedMemorySize, SM_MMA);
    cudaFuncSetAttribute(k_gates, cudaFuncAttributeMaxDynamicSharedMemorySize, SM_GATES);
    cudaFuncSetAttribute(k_alpha, cudaFuncAttributeMaxDynamicSharedMemorySize, SM_ALPHA);
    attr_done = true;
  }

  k_zero_adj<<<512, 256>>>();
  k_build_adj<<<NEDGE / 256, 256>>>(src, dst);
  k_pack<<<256, 256>>>(W_in, W_og, W_ih, W_hh, W_u, W_v, b_in, b_og, b_ih, b_hh);
  k_split_feat<<<2048, 256>>>(feat);

  // Y = feat @ [W_in;W_og]^T + biasY -> fused per-graph aggregation -> Agg hi/lo
  k_mma<EPI_AGG><<<dim3(NNODE / 128, 2), 256, SM_MMA>>>(
      featH, featL, 128, WioH, WioL, 128, biasY, nullptr, 0);

  // gates + fused GRU -> HN hi/lo
  k_gates<<<NNODE / 64, 256, SM_GATES>>>();

  // FV = hn[last] @ W_v^T + b_v
  k_mma<EPI_PLAIN><<<dim3(NGRAPH / 128, 1), 256, SM_MMA>>>(
      HNh + 31 * 128, HNl + 31 * 128, 4096, WvH, WvL, 128, b_v, FV, 128);

  // U GEMM + attention + readout -> out
  k_alpha<<<NNODE / 128, 256, SM_ALPHA>>>(cnt, w_e, out);
}

// round 6
// speedup vs baseline: 1.3281x; 1.3281x over previous
#include <cuda_runtime.h>
#include <cuda_fp16.h>
#include <cstdint>

#define NGRAPH 8192
#define NP 32
#define HDIM 128
#define NEDGE 524288
#define NNODE (NGRAPH * NP)

typedef __half h16;

// ================= static device scratch =================
__device__ __align__(16) int  g_adj[NGRAPH * 1024];
__device__ __align__(16) h16  g_featH[(size_t)NNODE * 128];
__device__ __align__(16) h16  g_featL[(size_t)NNODE * 128];
__device__ __align__(16) h16  g_AggH[(size_t)NNODE * 256];
__device__ __align__(16) h16  g_AggL[(size_t)NNODE * 256];
__device__ __align__(16) h16  g_HNh[(size_t)NNODE * 128];
__device__ __align__(16) h16  g_HNl[(size_t)NNODE * 128];
__device__ __align__(16) float g_FV[(size_t)NGRAPH * 128];
__device__ __align__(16) h16  g_Wio[256 * 128];   // single fp16 weights
__device__ __align__(16) h16  g_Wg[512 * 384];
__device__ __align__(16) h16  g_Wu[128 * 128];
__device__ __align__(16) h16  g_Wv[128 * 128];
__device__ __align__(16) float g_biasY[256];
__device__ __align__(16) float g_biasG[512];

// ================= helpers =================
__device__ __forceinline__ uint32_t smem_to_u32(const void* p) {
  uint32_t a;
  asm("{ .reg .u64 tmp; cvta.to.shared.u64 tmp, %1; cvt.u32.u64 %0, tmp; }"
      : "=r"(a) : "l"(p));
  return a;
}
#define SWZ(off) ((off) ^ (((off) >> 3) & 0x70))

__device__ __forceinline__ void cp16(uint32_t dst, const void* src) {
  asm volatile("cp.async.cg.shared.global [%0], [%1], 16;" ::"r"(dst), "l"(src));
}
#define CP_COMMIT() asm volatile("cp.async.commit_group;" ::: "memory")
#define CP_WAIT(n) asm volatile("cp.async.wait_group %0;" ::"n"(n) : "memory")

__device__ __forceinline__ void ldsm_x4(uint32_t addr, uint32_t* r) {
  asm volatile("ldmatrix.sync.aligned.m8n8.x4.shared.b16 {%0,%1,%2,%3}, [%4];"
               : "=r"(r[0]), "=r"(r[1]), "=r"(r[2]), "=r"(r[3]) : "r"(addr));
}
__device__ __forceinline__ void mma16816(float* d, const uint32_t* a,
                                         const uint32_t* b) {
  asm volatile(
      "mma.sync.aligned.m16n8k16.row.col.f32.f16.f16.f32 "
      "{%0,%1,%2,%3}, {%4,%5,%6,%7}, {%8,%9}, {%0,%1,%2,%3};"
      : "+f"(d[0]), "+f"(d[1]), "+f"(d[2]), "+f"(d[3])
      : "r"(a[0]), "r"(a[1]), "r"(a[2]), "r"(a[3]), "r"(b[0]), "r"(b[1]));
}

__device__ __forceinline__ float sigf(float x) { return 1.f / (1.f + __expf(-x)); }
__device__ __forceinline__ float tanh_fast(float x) {
  float e2x = __expf(2.f * x);
  return 1.f - 2.f / (e2x + 1.f);
}
__device__ __forceinline__ void split2h(float v, h16* hh, h16* ll) {
  h16 hi = __float2half_rn(v);
  *hh = hi;
  *ll = __float2half_rn(v - __half2float(hi));
}
__device__ __forceinline__ float h2f(h16 v) { return __half2float(v); }

// ================= adjacency =================
__global__ void k_zero_adj() {
  int i = blockIdx.x * blockDim.x + threadIdx.x;
  int stride = gridDim.x * blockDim.x;
  int4* p = (int4*)g_adj;
  const int n4 = NGRAPH * 1024 / 4;
  int4 z = make_int4(0, 0, 0, 0);
  for (; i < n4; i += stride) p[i] = z;
}
__global__ void k_build_adj(const int* __restrict__ src, const int* __restrict__ dst) {
  int e = blockIdx.x * blockDim.x + threadIdx.x;
  if (e >= NEDGE) return;
  int d = dst[e];
  int s = src[e];
  atomicAdd(&g_adj[((d >> 5) << 10) + ((d & 31) << 5) + (s & 31)], 1);
}

// ================= weight pack =================
__global__ void k_pack(const float* __restrict__ W_in, const float* __restrict__ W_og,
                       const float* __restrict__ W_ih, const float* __restrict__ W_hh,
                       const float* __restrict__ W_u, const float* __restrict__ W_v,
                       const float* __restrict__ b_in, const float* __restrict__ b_og,
                       const float* __restrict__ b_ih, const float* __restrict__ b_hh) {
  int i0 = blockIdx.x * 256 + threadIdx.x;
  int stride = gridDim.x * 256;
  for (int i = i0; i < 256 * 128; i += stride) {
    int r = i >> 7, c = i & 127;
    float v = (r < 128) ? W_in[r * 128 + c] : W_og[(r - 128) * 128 + c];
    g_Wio[i] = __float2half_rn(v);
  }
  for (int i = i0; i < 512 * 384; i += stride) {
    int r = i / 384, c = i % 384;
    int blk = r >> 7, rr = r & 127;
    float v;
    if (blk == 0)      v = (c < 256) ? W_ih[rr * 256 + c] : W_hh[rr * 128 + (c - 256)];
    else if (blk == 1) v = (c < 256) ? W_ih[(128 + rr) * 256 + c] : W_hh[(128 + rr) * 128 + (c - 256)];
    else if (blk == 2) v = (c < 256) ? W_ih[(256 + rr) * 256 + c] : 0.f;
    else               v = (c < 256) ? 0.f : W_hh[(256 + rr) * 128 + (c - 256)];
    g_Wg[i] = __float2half_rn(v);
  }
  for (int i = i0; i < 128 * 128; i += stride) {
    g_Wu[i] = __float2half_rn(W_u[i]);
    g_Wv[i] = __float2half_rn(W_v[i]);
  }
  for (int i = i0; i < 256; i += stride)
    g_biasY[i] = (i < 128) ? b_in[i] : b_og[i - 128];
  for (int i = i0; i < 512; i += stride) {
    float v;
    if (i < 256)      v = b_ih[i] + b_hh[i];
    else if (i < 384) v = b_ih[i];
    else              v = b_hh[i - 128];
    g_biasG[i] = v;
  }
}

__global__ void k_split_feat(const float* __restrict__ feat) {
  size_t i = (size_t)blockIdx.x * 256 + threadIdx.x;
  size_t stride = (size_t)gridDim.x * 256;
  const size_t n = (size_t)NNODE * 128;
  for (; i < n; i += stride) split2h(feat[i], &g_featH[i], &g_featL[i]);
}

// ================= generic GEMM: 128 thr, warp 64x64, fp16 2-pass ========
#define EPI_PLAIN 0
#define EPI_AGG 1

#define SG 49152
#define T_AH 0
#define T_AL 16384
#define T_B  32768

template <int EPI>
__global__ void __launch_bounds__(128, 2) k_mma(
    const h16* __restrict__ Ah, const h16* __restrict__ Al, int lda,
    const h16* __restrict__ Bh0, int ldb,
    const float* __restrict__ bias, float* __restrict__ C, int ldc) {
  extern __shared__ __align__(1024) char smem[];
  const uint32_t sb = smem_to_u32(smem);
  const int tid = threadIdx.x;
  const int lid = tid & 31, wid = tid >> 5;
  const int m0 = blockIdx.x * 128;
  const int nb = blockIdx.y;
  const int wm0 = (wid & 1) * 64, wn0 = (wid >> 1) * 64;

  const h16* Bh = Bh0 + (size_t)nb * 128 * ldb;
  const int nchunks = ldb >> 6;

  auto issue = [&](int kc, int s) {
    uint32_t base = sb + s * SG;
#pragma unroll
    for (int i = 0; i < 8; i++) {
      int u = tid + 128 * i;
      int r = u >> 3, seg = u & 7;
      uint32_t d = SWZ(r * 128 + seg * 16);
      size_t aoff = (size_t)(m0 + r) * lda + kc + seg * 8;
      cp16(base + T_AH + d, Ah + aoff);
      cp16(base + T_AL + d, Al + aoff);
      size_t boff = (size_t)r * ldb + kc + seg * 8;
      cp16(base + T_B + d, Bh + boff);
    }
    CP_COMMIT();
  };

  float acc[4][8][4];
#pragma unroll
  for (int mi = 0; mi < 4; mi++)
#pragma unroll
    for (int ni = 0; ni < 8; ni++)
#pragma unroll
      for (int q = 0; q < 4; q++) acc[mi][ni][q] = 0.f;

  issue(0, 0);
  for (int c = 0; c < nchunks; c++) {
    if (c + 1 < nchunks) { issue((c + 1) * 64, (c + 1) & 1); CP_WAIT(1); }
    else CP_WAIT(0);
    __syncthreads();
    const uint32_t st = sb + (c & 1) * SG;
    const int j = lid >> 3, rr = lid & 7;
#pragma unroll
    for (int kk = 0; kk < 4; kk++) {
      uint32_t ah[4][4], al[4][4], bh[8][2];
#pragma unroll
      for (int mi = 0; mi < 4; mi++) {
        int row = wm0 + mi * 16 + (j & 1) * 8 + rr;
        int kb = kk * 32 + (j >> 1) * 16;
        uint32_t ad = st + T_AH + SWZ(row * 128 + kb);
        ldsm_x4(ad, ah[mi]);
        ldsm_x4(ad + (T_AL - T_AH), al[mi]);
      }
#pragma unroll
      for (int p = 0; p < 4; p++) {
        int n = wn0 + p * 16 + (j >> 1) * 8 + rr;
        int kb = kk * 32 + (j & 1) * 16;
        uint32_t t[4];
        ldsm_x4(st + T_B + SWZ(n * 128 + kb), t);
        bh[2 * p][0] = t[0]; bh[2 * p][1] = t[1];
        bh[2 * p + 1][0] = t[2]; bh[2 * p + 1][1] = t[3];
      }
#pragma unroll
      for (int mi = 0; mi < 4; mi++)
#pragma unroll
        for (int ni = 0; ni < 8; ni++) {
          mma16816(acc[mi][ni], ah[mi], bh[ni]);
          mma16816(acc[mi][ni], al[mi], bh[ni]);
        }
    }
    __syncthreads();
  }

  const int gp = lid >> 2, tg = lid & 3;

  if (EPI == EPI_PLAIN) {
#pragma unroll
    for (int mi = 0; mi < 4; mi++)
#pragma unroll
      for (int ni = 0; ni < 8; ni++) {
        int r0 = m0 + wm0 + mi * 16 + gp;
        int c = wn0 + ni * 8 + tg * 2;
        float b0 = bias ? bias[c] : 0.f;
        float b1 = bias ? bias[c + 1] : 0.f;
        *(float2*)&C[(size_t)r0 * ldc + c] =
            make_float2(acc[mi][ni][0] + b0, acc[mi][ni][1] + b1);
        *(float2*)&C[(size_t)(r0 + 8) * ldc + c] =
            make_float2(acc[mi][ni][2] + b0, acc[mi][ni][3] + b1);
      }
  } else {  // EPI_AGG: per-graph aggregation fused
    float* sC = (float*)smem;  // [128][132]
#pragma unroll
    for (int mi = 0; mi < 4; mi++)
#pragma unroll
      for (int ni = 0; ni < 8; ni++) {
        int r = wm0 + mi * 16 + gp;
        int c = wn0 + ni * 8 + tg * 2;
        float b0 = bias[nb * 128 + c], b1 = bias[nb * 128 + c + 1];
        sC[r * 132 + c] = acc[mi][ni][0] + b0;
        sC[r * 132 + c + 1] = acc[mi][ni][1] + b1;
        sC[(r + 8) * 132 + c] = acc[mi][ni][2] + b0;
        sC[(r + 8) * 132 + c + 1] = acc[mi][ni][3] + b1;
      }
    float* adjf = (float*)(smem + 67584);            // 4 x [32][33]
    float* rdeg = (float*)(smem + 67584 + 16896);    // [128]
    const int g0 = m0 >> 5;
    for (int i = tid; i < 4096; i += 128) {
      int gl = i >> 10, rem = i & 1023;
      adjf[gl * 1056 + (rem >> 5) * 33 + (rem & 31)] =
          (float)g_adj[((g0 + gl) << 10) + rem];
    }
    __syncthreads();
    {
      int gl = tid >> 5, n = tid & 31;
      float s = 0.f;
#pragma unroll
      for (int k = 0; k < 32; k++)
        s += (nb == 0) ? adjf[gl * 1056 + n * 33 + k]
                       : adjf[gl * 1056 + k * 33 + n];
      rdeg[tid] = 1.f / fmaxf(s, 1.f);
    }
    __syncthreads();
    const int gl = tid >> 5, jj = tid & 31;
    float ac[4][32];
#pragma unroll
    for (int cq = 0; cq < 4; cq++)
#pragma unroll
      for (int n = 0; n < 32; n++) ac[cq][n] = 0.f;
    for (int k = 0; k < 32; k++) {
      float cv[4];
#pragma unroll
      for (int cq = 0; cq < 4; cq++)
        cv[cq] = sC[(gl * 32 + k) * 132 + jj + cq * 32];
#pragma unroll
      for (int n = 0; n < 32; n++) {
        float w = (nb == 0) ? adjf[gl * 1056 + n * 33 + k]
                            : adjf[gl * 1056 + k * 33 + n];
#pragma unroll
        for (int cq = 0; cq < 4; cq++) ac[cq][n] += w * cv[cq];
      }
    }
#pragma unroll
    for (int n = 0; n < 32; n++) {
      float rd = rdeg[gl * 32 + n];
      size_t o = (size_t)(m0 + gl * 32 + n) * 256 + nb * 128 + jj;
#pragma unroll
      for (int cq = 0; cq < 4; cq++) {
        float v = ac[cq][n] * rd;
        split2h(v, &g_AggH[o + cq * 32], &g_AggL[o + cq * 32]);
      }
    }
  }
}

// ================= gates GEMM + fused GRU =================
// BM=64, 8 warps: warp-pair per gate (warp tile 32x128). 6 K64 chunks.
#define GSG 65536
#define G_AH 0
#define G_AL 8192
#define G_B0 16384    // + slot*16384

__global__ void __launch_bounds__(256, 1) k_gates() {
  extern __shared__ __align__(1024) char smem[];
  const uint32_t sb = smem_to_u32(smem);
  float* sbias = (float*)(smem + 2 * GSG);
  const int tid = threadIdx.x;
  const int lid = tid & 31, wid = tid >> 5;
  const int m0 = blockIdx.x * 64;
  const int gate = wid >> 1;
  const int wm0 = (wid & 1) * 32;

  for (int i = tid; i < 512; i += 256) sbias[i] = g_biasG[i];

  auto issue = [&](int ch) {
    int kc = ch * 64;
    bool isFeat = ch >= 4;
    uint32_t base = sb + (ch & 1) * GSG;
    const h16* ah = isFeat ? g_featH : g_AggH;
    const h16* al = isFeat ? g_featL : g_AggL;
    int ld = isFeat ? 128 : 256;
    int kk = isFeat ? kc - 256 : kc;
    // A: 64 rows x 64 cols hi+lo = 512 lines each
#pragma unroll
    for (int i = 0; i < 2; i++) {
      int u = tid + 256 * i;
      int r = u >> 3, seg = u & 7;
      uint32_t d = SWZ(r * 128 + seg * 16);
      size_t aoff = (size_t)(m0 + r) * ld + kk + seg * 8;
      cp16(base + G_AH + d, ah + aoff);
      cp16(base + G_AL + d, al + aoff);
    }
    // B: 3 slots x (128 rows x 64 cols)
#pragma unroll
    for (int slot = 0; slot < 3; slot++) {
      int bg = (slot < 2) ? slot : (isFeat ? 3 : 2);
#pragma unroll
      for (int i = 0; i < 4; i++) {
        int u = tid + 256 * i;
        int r = u >> 3, seg = u & 7;
        uint32_t d = SWZ(r * 128 + seg * 16);
        size_t boff = (size_t)(bg * 128 + r) * 384 + kc + seg * 8;
        cp16(base + G_B0 + slot * 16384 + d, g_Wg + boff);
      }
    }
    CP_COMMIT();
  };

  float acc[2][16][4];
#pragma unroll
  for (int mi = 0; mi < 2; mi++)
#pragma unroll
    for (int ni = 0; ni < 16; ni++)
#pragma unroll
      for (int q = 0; q < 4; q++) acc[mi][ni][q] = 0.f;

  issue(0);
  for (int ch = 0; ch < 6; ch++) {
    if (ch + 1 < 6) { issue(ch + 1); CP_WAIT(1); }
    else CP_WAIT(0);
    __syncthreads();
    bool active = (gate == 2) ? (ch < 4) : (gate == 3) ? (ch >= 4) : true;
    if (active) {
      const uint32_t st = sb + (ch & 1) * GSG;
      const int bslot = (gate < 2) ? gate : 2;
      const uint32_t bbase = st + G_B0 + bslot * 16384;
      const int j = lid >> 3, rr = lid & 7;
#pragma unroll
      for (int kk = 0; kk < 4; kk++) {
        uint32_t ah[2][4], al[2][4], bh[16][2];
#pragma unroll
        for (int mi = 0; mi < 2; mi++) {
          int row = wm0 + mi * 16 + (j & 1) * 8 + rr;
          int kb = kk * 32 + (j >> 1) * 16;
          uint32_t ad = st + G_AH + SWZ(row * 128 + kb);
          ldsm_x4(ad, ah[mi]);
          ldsm_x4(ad + (G_AL - G_AH), al[mi]);
        }
#pragma unroll
        for (int p = 0; p < 8; p++) {
          int n = p * 16 + (j >> 1) * 8 + rr;
          int kb = kk * 32 + (j & 1) * 16;
          uint32_t t[4];
          ldsm_x4(bbase + SWZ(n * 128 + kb), t);
          bh[2 * p][0] = t[0]; bh[2 * p][1] = t[1];
          bh[2 * p + 1][0] = t[2]; bh[2 * p + 1][1] = t[3];
        }
#pragma unroll
        for (int mi = 0; mi < 2; mi++)
#pragma unroll
          for (int ni = 0; ni < 16; ni++) {
            mma16816(acc[mi][ni], ah[mi], bh[ni]);
            mma16816(acc[mi][ni], al[mi], bh[ni]);
          }
      }
    }
    __syncthreads();
  }

  // ---- extract feat (chunks 4,5 = stages 0,1) to registers ----
  const int frow = tid >> 2;          // 0..63
  const int fc0 = (tid & 3) * 32;     // col base
  float fv[32];
#pragma unroll
  for (int c = 0; c < 32; c++) {
    int col = fc0 + c;
    int stg = col >> 6, cidx = col & 63;
    uint32_t off = SWZ(frow * 128 + cidx * 2);
    fv[c] = h2f(*(h16*)(smem + stg * GSG + G_AH + off)) +
            h2f(*(h16*)(smem + stg * GSG + G_AL + off));
  }
  __syncthreads();

  // ---- stash gate accumulators to smem sG[4][64][128] f32 ----
  float* sG = (float*)smem;
  const int gp = lid >> 2, tg = lid & 3;
#pragma unroll
  for (int mi = 0; mi < 2; mi++)
#pragma unroll
    for (int ni = 0; ni < 16; ni++) {
      int r = wm0 + mi * 16 + gp;
      int c = ni * 8 + tg * 2;
      sG[gate * 8192 + r * 128 + c] = acc[mi][ni][0];
      sG[gate * 8192 + r * 128 + c + 1] = acc[mi][ni][1];
      sG[gate * 8192 + (r + 8) * 128 + c] = acc[mi][ni][2];
      sG[gate * 8192 + (r + 8) * 128 + c + 1] = acc[mi][ni][3];
    }
  __syncthreads();

  // ---- GRU elementwise -> HN hi/lo ----
  __align__(16) h16 oh[32], ol[32];
#pragma unroll
  for (int c = 0; c < 32; c++) {
    int col = fc0 + c;
    float rs = sG[frow * 128 + col] + sbias[col];
    float zs = sG[8192 + frow * 128 + col] + sbias[128 + col];
    float is = sG[2 * 8192 + frow * 128 + col] + sbias[256 + col];
    float hs = sG[3 * 8192 + frow * 128 + col] + sbias[384 + col];
    float r_ = sigf(rs), z_ = sigf(zs);
    float ng = tanh_fast(is + r_ * hs);
    float hn = (1.f - z_) * ng + z_ * fv[c];
    split2h(hn, &oh[c], &ol[c]);
  }
  {
    size_t o = (size_t)(m0 + frow) * 128 + fc0;
    int4* dh = (int4*)&g_HNh[o];
    int4* dl = (int4*)&g_HNl[o];
#pragma unroll
    for (int q = 0; q < 4; q++) {
      dh[q] = ((int4*)oh)[q];
      dl[q] = ((int4*)ol)[q];
    }
  }
}

// ================= U GEMM + attention + readout fused =================
__global__ void __launch_bounds__(128, 2) k_alpha(const float* __restrict__ cnt,
                                                  const float* __restrict__ we,
                                                  float* __restrict__ out) {
  extern __shared__ __align__(1024) char smem[];
  const uint32_t sb = smem_to_u32(smem);
  const int tid = threadIdx.x;
  const int lid = tid & 31, wid = tid >> 5;
  const int m0 = blockIdx.x * 128;
  const int g0 = m0 >> 5;
  const int wm0 = (wid & 1) * 64, wn0 = (wid >> 1) * 64;

  float* sFV = (float*)(smem + 2 * SG);   // [4][128]
  float* swe = sFV + 512;
  float* scnt = swe + 128;
  float* sPart = scnt + 128;              // [2][128]
  float* sAl = sPart + 256;               // [128]

  for (int i = tid; i < 512; i += 128)
    sFV[i] = g_FV[(size_t)(g0 + (i >> 7)) * 128 + (i & 127)];
  if (tid < 128) { swe[tid] = we[tid]; scnt[tid] = cnt[m0 + tid]; }

  auto issue = [&](int kc, int s) {
    uint32_t base = sb + s * SG;
#pragma unroll
    for (int i = 0; i < 8; i++) {
      int u = tid + 128 * i;
      int r = u >> 3, seg = u & 7;
      uint32_t d = SWZ(r * 128 + seg * 16);
      size_t aoff = (size_t)(m0 + r) * 128 + kc + seg * 8;
      cp16(base + T_AH + d, g_HNh + aoff);
      cp16(base + T_AL + d, g_HNl + aoff);
      size_t boff = (size_t)r * 128 + kc + seg * 8;
      cp16(base + T_B + d, g_Wu + boff);
    }
    CP_COMMIT();
  };

  float acc[4][8][4];
#pragma unroll
  for (int mi = 0; mi < 4; mi++)
#pragma unroll
    for (int ni = 0; ni < 8; ni++)
#pragma unroll
      for (int q = 0; q < 4; q++) acc[mi][ni][q] = 0.f;

  issue(0, 0);
  issue(64, 1);
  for (int c = 0; c < 2; c++) {
    if (c == 0) CP_WAIT(1); else CP_WAIT(0);
    __syncthreads();
    const uint32_t st = sb + c * SG;
    const int j = lid >> 3, rr = lid & 7;
#pragma unroll
    for (int kk = 0; kk < 4; kk++) {
      uint32_t ah[4][4], al[4][4], bh[8][2];
#pragma unroll
      for (int mi = 0; mi < 4; mi++) {
        int row = wm0 + mi * 16 + (j & 1) * 8 + rr;
        int kb = kk * 32 + (j >> 1) * 16;
        uint32_t ad = st + T_AH + SWZ(row * 128 + kb);
        ldsm_x4(ad, ah[mi]);
        ldsm_x4(ad + (T_AL - T_AH), al[mi]);
      }
#pragma unroll
      for (int p = 0; p < 4; p++) {
        int n = wn0 + p * 16 + (j >> 1) * 8 + rr;
        int kb = kk * 32 + (j & 1) * 16;
        uint32_t t[4];
        ldsm_x4(st + T_B + SWZ(n * 128 + kb), t);
        bh[2 * p][0] = t[0]; bh[2 * p][1] = t[1];
        bh[2 * p + 1][0] = t[2]; bh[2 * p + 1][1] = t[3];
      }
#pragma unroll
      for (int mi = 0; mi < 4; mi++)
#pragma unroll
        for (int ni = 0; ni < 8; ni++) {
          mma16816(acc[mi][ni], ah[mi], bh[ni]);
          mma16816(acc[mi][ni], al[mi], bh[ni]);
        }
    }
    __syncthreads();
  }

  // attention: e[row] = sum_j we[j]*sig(U[row][j] + FV[g][j])
  const int gp = lid >> 2, tg = lid & 3;
#pragma unroll
  for (int mi = 0; mi < 4; mi++) {
    int base = wm0 + mi * 16;
    int gl = base >> 5;
    float p0 = 0.f, p1 = 0.f;
#pragma unroll
    for (int ni = 0; ni < 8; ni++) {
      int jx = wn0 + ni * 8 + tg * 2;
      float fv0 = sFV[gl * 128 + jx], fv1 = sFV[gl * 128 + jx + 1];
      float w0 = swe[jx], w1 = swe[jx + 1];
      p0 += w0 * sigf(acc[mi][ni][0] + fv0) + w1 * sigf(acc[mi][ni][1] + fv1);
      p1 += w0 * sigf(acc[mi][ni][2] + fv0) + w1 * sigf(acc[mi][ni][3] + fv1);
    }
    p0 += __shfl_xor_sync(0xffffffffu, p0, 1);
    p0 += __shfl_xor_sync(0xffffffffu, p0, 2);
    p1 += __shfl_xor_sync(0xffffffffu, p1, 1);
    p1 += __shfl_xor_sync(0xffffffffu, p1, 2);
    if (tg == 0) {
      sPart[(wn0 >> 6) * 128 + base + gp] = p0;
      sPart[(wn0 >> 6) * 128 + base + gp + 8] = p1;
    }
  }
  __syncthreads();
  if (tid < 128)
    sAl[tid] = (sPart[tid] + sPart[128 + tid]) * scnt[tid];
  __syncthreads();

  // readout: hn reconstructed from HN hi/lo tiles still in both stages
#pragma unroll
  for (int v = 0; v < 4; v++) {
    int idx = tid + v * 128;
    int gl = idx >> 7, jx = idx & 127;
    int stg = jx >> 6, cidx = jx & 63;
    float accg = 0.f, hn31 = 0.f;
#pragma unroll
    for (int n = 0; n < 32; n++) {
      int rowl = gl * 32 + n;
      uint32_t off = SWZ(rowl * 128 + cidx * 2);
      float hn = h2f(*(h16*)(smem + stg * SG + T_AH + off)) +
                 h2f(*(h16*)(smem + stg * SG + T_AL + off));
      accg += hn * sAl[rowl];
      if (n == 31) hn31 = hn;
    }
    out[(size_t)(g0 + gl) * 256 + jx] = accg;
    out[(size_t)(g0 + gl) * 256 + 128 + jx] = hn31;
  }
}

// ================= host =================
extern "C" void kernel_launch(void* const* d_in, const int* in_sizes, int n_in,
                              void* d_out, int out_size) {
  const float* feat = (const float*)d_in[0];
  const float* cnt  = (const float*)d_in[1];
  const float* W_in = (const float*)d_in[2];
  const float* b_in = (const float*)d_in[3];
  const float* W_og = (const float*)d_in[4];
  const float* b_og = (const float*)d_in[5];
  const float* W_ih = (const float*)d_in[6];
  const float* b_ih = (const float*)d_in[7];
  const float* W_hh = (const float*)d_in[8];
  const float* b_hh = (const float*)d_in[9];
  const float* W_u  = (const float*)d_in[10];
  const float* W_v  = (const float*)d_in[11];
  const float* b_v  = (const float*)d_in[12];
  const float* w_e  = (const float*)d_in[13];
  const int*   src  = (const int*)d_in[14];
  const int*   dst  = (const int*)d_in[15];
  float* out = (float*)d_out;

  h16 *featH, *featL, *HNh, *HNl, *Wio, *Wv;
  float *FV, *biasY;
  cudaGetSymbolAddress((void**)&featH, g_featH);
  cudaGetSymbolAddress((void**)&featL, g_featL);
  cudaGetSymbolAddress((void**)&HNh, g_HNh);
  cudaGetSymbolAddress((void**)&HNl, g_HNl);
  cudaGetSymbolAddress((void**)&FV, g_FV);
  cudaGetSymbolAddress((void**)&Wio, g_Wio);
  cudaGetSymbolAddress((void**)&Wv, g_Wv);
  cudaGetSymbolAddress((void**)&biasY, g_biasY);

  const int SM_MMA = 2 * SG;                 // 98304
  const int SM_GATES = 2 * GSG + 2048;       // 133120
  const int SM_ALPHA = 2 * SG + 4608;        // 102912
  static bool attr_done = false;
  if (!attr_done) {
    cudaFuncSetAttribute(k_mma<EPI_PLAIN>, cudaFuncAttributeMaxDynamicSharedMemorySize, SM_MMA);
    cudaFuncSetAttribute(k_mma<EPI_AGG>, cudaFuncAttributeMaxDynamicSharedMemorySize, SM_MMA);
    cudaFuncSetAttribute(k_gates, cudaFuncAttributeMaxDynamicSharedMemorySize, SM_GATES);
    cudaFuncSetAttribute(k_alpha, cudaFuncAttributeMaxDynamicSharedMemorySize, SM_ALPHA);
    attr_done = true;
  }

  k_zero_adj<<<512, 256>>>();
  k_build_adj<<<NEDGE / 256, 256>>>(src, dst);
  k_pack<<<256, 256>>>(W_in, W_og, W_ih, W_hh, W_u, W_v, b_in, b_og, b_ih, b_hh);
  k_split_feat<<<2048, 256>>>(feat);

  // Y = feat @ [W_in;W_og]^T + biasY -> fused per-graph aggregation -> Agg hi/lo
  k_mma<EPI_AGG><<<dim3(NNODE / 128, 2), 128, SM_MMA>>>(
      featH, featL, 128, Wio, 128, biasY, nullptr, 0);

  // gates + fused GRU -> HN hi/lo
  k_gates<<<NNODE / 64, 256, SM_GATES>>>();

  // FV = hn[last] @ W_v^T + b_v
  k_mma<EPI_PLAIN><<<dim3(NGRAPH / 128, 1), 128, SM_MMA>>>(
      HNh + 31 * 128, HNl + 31 * 128, 4096, Wv, 128, b_v, FV, 128);

  // U GEMM + attention + readout -> out
  k_alpha<<<NNODE / 128, 128, SM_ALPHA>>>(cnt, w_e, out);
}

// round 7
// speedup vs baseline: 1.3575x; 1.0221x over previous
#include <cuda_runtime.h>
#include <cuda_fp16.h>
#include <cstdint>

#define NGRAPH 8192
#define NP 32
#define HDIM 128
#define NEDGE 524288
#define NNODE (NGRAPH * NP)

typedef __half h16;

// ================= static device scratch =================
__device__ __align__(16) int  g_adj[NGRAPH * 1024];
__device__ __align__(16) h16  g_featH[(size_t)NNODE * 128];
__device__ __align__(16) h16  g_AggH[(size_t)NNODE * 256];
__device__ __align__(16) h16  g_HNh[(size_t)NNODE * 128];
__device__ __align__(16) float g_HNlast[(size_t)NGRAPH * 128];
__device__ __align__(16) float g_FV[(size_t)NGRAPH * 128];
__device__ __align__(16) h16  g_Wio[256 * 128];
__device__ __align__(16) h16  g_Wg[512 * 384];
__device__ __align__(16) h16  g_Wu[128 * 128];
__device__ __align__(16) h16  g_Wv[128 * 128];
__device__ __align__(16) float g_biasY[256];
__device__ __align__(16) float g_biasG[512];

// ================= helpers =================
__device__ __forceinline__ uint32_t smem_to_u32(const void* p) {
  uint32_t a;
  asm("{ .reg .u64 tmp; cvta.to.shared.u64 tmp, %1; cvt.u32.u64 %0, tmp; }"
      : "=r"(a) : "l"(p));
  return a;
}
#define SWZ(off) ((off) ^ (((off) >> 3) & 0x70))

__device__ __forceinline__ void cp16(uint32_t dst, const void* src) {
  asm volatile("cp.async.cg.shared.global [%0], [%1], 16;" ::"r"(dst), "l"(src));
}
#define CP_COMMIT() asm volatile("cp.async.commit_group;" ::: "memory")
#define CP_WAIT(n) asm volatile("cp.async.wait_group %0;" ::"n"(n) : "memory")

__device__ __forceinline__ void ldsm_x4(uint32_t addr, uint32_t* r) {
  asm volatile("ldmatrix.sync.aligned.m8n8.x4.shared.b16 {%0,%1,%2,%3}, [%4];"
               : "=r"(r[0]), "=r"(r[1]), "=r"(r[2]), "=r"(r[3]) : "r"(addr));
}
__device__ __forceinline__ void mma16816(float* d, const uint32_t* a,
                                         const uint32_t* b) {
  asm volatile(
      "mma.sync.aligned.m16n8k16.row.col.f32.f16.f16.f32 "
      "{%0,%1,%2,%3}, {%4,%5,%6,%7}, {%8,%9}, {%0,%1,%2,%3};"
      : "+f"(d[0]), "+f"(d[1]), "+f"(d[2]), "+f"(d[3])
      : "r"(a[0]), "r"(a[1]), "r"(a[2]), "r"(a[3]), "r"(b[0]), "r"(b[1]));
}

__device__ __forceinline__ float sigf(float x) { return 1.f / (1.f + __expf(-x)); }
__device__ __forceinline__ float tanh_fast(float x) {
  float e2x = __expf(2.f * x);
  return 1.f - 2.f / (e2x + 1.f);
}
__device__ __forceinline__ float h2f(h16 v) { return __half2float(v); }

// ================= adjacency =================
__global__ void k_zero_adj() {
  int i = blockIdx.x * blockDim.x + threadIdx.x;
  int stride = gridDim.x * blockDim.x;
  int4* p = (int4*)g_adj;
  const int n4 = NGRAPH * 1024 / 4;
  int4 z = make_int4(0, 0, 0, 0);
  for (; i < n4; i += stride) p[i] = z;
}
__global__ void k_build_adj(const int* __restrict__ src, const int* __restrict__ dst) {
  int e = blockIdx.x * blockDim.x + threadIdx.x;
  if (e >= NEDGE) return;
  int d = dst[e];
  int s = src[e];
  atomicAdd(&g_adj[((d >> 5) << 10) + ((d & 31) << 5) + (s & 31)], 1);
}

// ================= weight pack =================
__global__ void k_pack(const float* __restrict__ W_in, const float* __restrict__ W_og,
                       const float* __restrict__ W_ih, const float* __restrict__ W_hh,
                       const float* __restrict__ W_u, const float* __restrict__ W_v,
                       const float* __restrict__ b_in, const float* __restrict__ b_og,
                       const float* __restrict__ b_ih, const float* __restrict__ b_hh) {
  int i0 = blockIdx.x * 256 + threadIdx.x;
  int stride = gridDim.x * 256;
  for (int i = i0; i < 256 * 128; i += stride) {
    int r = i >> 7, c = i & 127;
    float v = (r < 128) ? W_in[r * 128 + c] : W_og[(r - 128) * 128 + c];
    g_Wio[i] = __float2half_rn(v);
  }
  for (int i = i0; i < 512 * 384; i += stride) {
    int r = i / 384, c = i % 384;
    int blk = r >> 7, rr = r & 127;
    float v;
    if (blk == 0)      v = (c < 256) ? W_ih[rr * 256 + c] : W_hh[rr * 128 + (c - 256)];
    else if (blk == 1) v = (c < 256) ? W_ih[(128 + rr) * 256 + c] : W_hh[(128 + rr) * 128 + (c - 256)];
    else if (blk == 2) v = (c < 256) ? W_ih[(256 + rr) * 256 + c] : 0.f;
    else               v = (c < 256) ? 0.f : W_hh[(256 + rr) * 128 + (c - 256)];
    g_Wg[i] = __float2half_rn(v);
  }
  for (int i = i0; i < 128 * 128; i += stride) {
    g_Wu[i] = __float2half_rn(W_u[i]);
    g_Wv[i] = __float2half_rn(W_v[i]);
  }
  for (int i = i0; i < 256; i += stride)
    g_biasY[i] = (i < 128) ? b_in[i] : b_og[i - 128];
  for (int i = i0; i < 512; i += stride) {
    float v;
    if (i < 256)      v = b_ih[i] + b_hh[i];
    else if (i < 384) v = b_ih[i];
    else              v = b_hh[i - 128];
    g_biasG[i] = v;
  }
}

__global__ void k_conv_feat(const float* __restrict__ feat) {
  size_t i = (size_t)blockIdx.x * blockDim.x + threadIdx.x;
  size_t stride = (size_t)gridDim.x * blockDim.x;
  const float4* f4 = (const float4*)feat;
  const size_t n4 = (size_t)NNODE * 32;
  for (; i < n4; i += stride) {
    float4 v = f4[i];
    __half2 a = __floats2half2_rn(v.x, v.y);
    __half2 b = __floats2half2_rn(v.z, v.w);
    __half2* dst = (__half2*)&g_featH[i * 4];
    dst[0] = a;
    dst[1] = b;
  }
}

// ================= generic GEMM: 128 thr, warp 64x64, single-pass fp16 ====
#define EPI_PLAIN 0
#define EPI_AGG 1

#define SG 32768
#define T_A 0
#define T_B 16384

template <int EPI>
__global__ void __launch_bounds__(128, 2) k_mma(
    const h16* __restrict__ Ah, int lda,
    const h16* __restrict__ Bh0, int ldb,
    const float* __restrict__ bias, float* __restrict__ C, int ldc) {
  extern __shared__ __align__(1024) char smem[];
  const uint32_t sb = smem_to_u32(smem);
  const int tid = threadIdx.x;
  const int lid = tid & 31, wid = tid >> 5;
  const int m0 = blockIdx.x * 128;
  const int nb = blockIdx.y;
  const int wm0 = (wid & 1) * 64, wn0 = (wid >> 1) * 64;

  const h16* Bh = Bh0 + (size_t)nb * 128 * ldb;
  const int nchunks = ldb >> 6;

  auto issue = [&](int kc, int s) {
    uint32_t base = sb + s * SG;
#pragma unroll
    for (int i = 0; i < 8; i++) {
      int u = tid + 128 * i;
      int r = u >> 3, seg = u & 7;
      uint32_t d = SWZ(r * 128 + seg * 16);
      cp16(base + T_A + d, Ah + (size_t)(m0 + r) * lda + kc + seg * 8);
      cp16(base + T_B + d, Bh + (size_t)r * ldb + kc + seg * 8);
    }
    CP_COMMIT();
  };

  float acc[4][8][4];
#pragma unroll
  for (int mi = 0; mi < 4; mi++)
#pragma unroll
    for (int ni = 0; ni < 8; ni++)
#pragma unroll
      for (int q = 0; q < 4; q++) acc[mi][ni][q] = 0.f;

  issue(0, 0);
  for (int c = 0; c < nchunks; c++) {
    if (c + 1 < nchunks) { issue((c + 1) * 64, (c + 1) & 1); CP_WAIT(1); }
    else CP_WAIT(0);
    __syncthreads();
    const uint32_t st = sb + (c & 1) * SG;
    const int j = lid >> 3, rr = lid & 7;
#pragma unroll
    for (int kk = 0; kk < 4; kk++) {
      uint32_t ah[4][4], bh[8][2];
#pragma unroll
      for (int mi = 0; mi < 4; mi++) {
        int row = wm0 + mi * 16 + (j & 1) * 8 + rr;
        int kb = kk * 32 + (j >> 1) * 16;
        ldsm_x4(st + T_A + SWZ(row * 128 + kb), ah[mi]);
      }
#pragma unroll
      for (int p = 0; p < 4; p++) {
        int n = wn0 + p * 16 + (j >> 1) * 8 + rr;
        int kb = kk * 32 + (j & 1) * 16;
        uint32_t t[4];
        ldsm_x4(st + T_B + SWZ(n * 128 + kb), t);
        bh[2 * p][0] = t[0]; bh[2 * p][1] = t[1];
        bh[2 * p + 1][0] = t[2]; bh[2 * p + 1][1] = t[3];
      }
#pragma unroll
      for (int mi = 0; mi < 4; mi++)
#pragma unroll
        for (int ni = 0; ni < 8; ni++)
          mma16816(acc[mi][ni], ah[mi], bh[ni]);
    }
    __syncthreads();
  }

  const int gp = lid >> 2, tg = lid & 3;

  if (EPI == EPI_PLAIN) {
#pragma unroll
    for (int mi = 0; mi < 4; mi++)
#pragma unroll
      for (int ni = 0; ni < 8; ni++) {
        int r0 = m0 + wm0 + mi * 16 + gp;
        int c = wn0 + ni * 8 + tg * 2;
        float b0 = bias ? bias[c] : 0.f;
        float b1 = bias ? bias[c + 1] : 0.f;
        *(float2*)&C[(size_t)r0 * ldc + c] =
            make_float2(acc[mi][ni][0] + b0, acc[mi][ni][1] + b1);
        *(float2*)&C[(size_t)(r0 + 8) * ldc + c] =
            make_float2(acc[mi][ni][2] + b0, acc[mi][ni][3] + b1);
      }
  } else {  // EPI_AGG: per-graph aggregation fused
    float* sC = (float*)smem;  // [128][132]
#pragma unroll
    for (int mi = 0; mi < 4; mi++)
#pragma unroll
      for (int ni = 0; ni < 8; ni++) {
        int r = wm0 + mi * 16 + gp;
        int c = wn0 + ni * 8 + tg * 2;
        float b0 = bias[nb * 128 + c], b1 = bias[nb * 128 + c + 1];
        sC[r * 132 + c] = acc[mi][ni][0] + b0;
        sC[r * 132 + c + 1] = acc[mi][ni][1] + b1;
        sC[(r + 8) * 132 + c] = acc[mi][ni][2] + b0;
        sC[(r + 8) * 132 + c + 1] = acc[mi][ni][3] + b1;
      }
    float* adjf = (float*)(smem + 67584);            // 4 x [32][33]
    float* rdeg = (float*)(smem + 67584 + 16896);    // [128]
    const int g0 = m0 >> 5;
    for (int i = tid; i < 4096; i += 128) {
      int gl = i >> 10, rem = i & 1023;
      adjf[gl * 1056 + (rem >> 5) * 33 + (rem & 31)] =
          (float)g_adj[((g0 + gl) << 10) + rem];
    }
    __syncthreads();
    {
      int gl = tid >> 5, n = tid & 31;
      float s = 0.f;
#pragma unroll
      for (int k = 0; k < 32; k++)
        s += (nb == 0) ? adjf[gl * 1056 + n * 33 + k]
                       : adjf[gl * 1056 + k * 33 + n];
      rdeg[tid] = 1.f / fmaxf(s, 1.f);
    }
    __syncthreads();
    const int gl = tid >> 5, jj = tid & 31;
    float ac[4][32];
#pragma unroll
    for (int cq = 0; cq < 4; cq++)
#pragma unroll
      for (int n = 0; n < 32; n++) ac[cq][n] = 0.f;
    for (int k = 0; k < 32; k++) {
      float cv[4];
#pragma unroll
      for (int cq = 0; cq < 4; cq++)
        cv[cq] = sC[(gl * 32 + k) * 132 + jj + cq * 32];
#pragma unroll
      for (int n = 0; n < 32; n++) {
        float w = (nb == 0) ? adjf[gl * 1056 + n * 33 + k]
                            : adjf[gl * 1056 + k * 33 + n];
#pragma unroll
        for (int cq = 0; cq < 4; cq++) ac[cq][n] += w * cv[cq];
      }
    }
#pragma unroll
    for (int n = 0; n < 32; n++) {
      float rd = rdeg[gl * 32 + n];
      size_t o = (size_t)(m0 + gl * 32 + n) * 256 + nb * 128 + jj;
#pragma unroll
      for (int cq = 0; cq < 4; cq++)
        g_AggH[o + cq * 32] = __float2half_rn(ac[cq][n] * rd);
    }
  }
}

// ================= gates GEMM + fused GRU (3-stage pipeline) =============
// BM=64, 8 warps: warp-pair per gate (warp tile 32x128). 6 K64 chunks.
#define GSG 57344
#define G_A 0
#define G_B0 8192

__global__ void __launch_bounds__(256, 1) k_gates() {
  extern __shared__ __align__(1024) char smem[];
  const uint32_t sb = smem_to_u32(smem);
  float* sbias = (float*)(smem + 3 * GSG);
  const int tid = threadIdx.x;
  const int lid = tid & 31, wid = tid >> 5;
  const int m0 = blockIdx.x * 64;
  const int gate = wid >> 1;
  const int wm0 = (wid & 1) * 32;

  for (int i = tid; i < 512; i += 256) sbias[i] = g_biasG[i];

  auto issue = [&](int ch) {
    int kc = ch * 64;
    bool isFeat = ch >= 4;
    uint32_t base = sb + (ch % 3) * GSG;
    const h16* ah = isFeat ? g_featH : g_AggH;
    int ld = isFeat ? 128 : 256;
    int kk = isFeat ? kc - 256 : kc;
    {
      int u = tid;  // 512 lines, 2 per thread
#pragma unroll
      for (int i = 0; i < 2; i++, u += 256) {
        int r = u >> 3, seg = u & 7;
        cp16(base + G_A + SWZ(r * 128 + seg * 16),
             ah + (size_t)(m0 + r) * ld + kk + seg * 8);
      }
    }
#pragma unroll
    for (int slot = 0; slot < 3; slot++) {
      int bg = (slot < 2) ? slot : (isFeat ? 3 : 2);
      int u = tid;
#pragma unroll
      for (int i = 0; i < 4; i++, u += 256) {
        int r = u >> 3, seg = u & 7;
        cp16(base + G_B0 + slot * 16384 + SWZ(r * 128 + seg * 16),
             g_Wg + (size_t)(bg * 128 + r) * 384 + kc + seg * 8);
      }
    }
    CP_COMMIT();
  };

  float acc[2][16][4];
#pragma unroll
  for (int mi = 0; mi < 2; mi++)
#pragma unroll
    for (int ni = 0; ni < 16; ni++)
#pragma unroll
      for (int q = 0; q < 4; q++) acc[mi][ni][q] = 0.f;

  issue(0);
  issue(1);
  for (int ch = 0; ch < 6; ch++) {
    __syncthreads();
    if (ch < 4) { issue(ch + 2); CP_WAIT(2); }
    else if (ch == 4) CP_WAIT(1);
    else CP_WAIT(0);
    __syncthreads();
    bool active = (gate == 2) ? (ch < 4) : (gate == 3) ? (ch >= 4) : true;
    if (active) {
      const uint32_t st = sb + (ch % 3) * GSG;
      const int bslot = (gate < 2) ? gate : 2;
      const uint32_t bbase = st + G_B0 + bslot * 16384;
      const int j = lid >> 3, rr = lid & 7;
#pragma unroll
      for (int kk = 0; kk < 4; kk++) {
        uint32_t ah[2][4], bh[16][2];
#pragma unroll
        for (int mi = 0; mi < 2; mi++) {
          int row = wm0 + mi * 16 + (j & 1) * 8 + rr;
          int kb = kk * 32 + (j >> 1) * 16;
          ldsm_x4(st + G_A + SWZ(row * 128 + kb), ah[mi]);
        }
#pragma unroll
        for (int p = 0; p < 8; p++) {
          int n = p * 16 + (j >> 1) * 8 + rr;
          int kb = kk * 32 + (j & 1) * 16;
          uint32_t t[4];
          ldsm_x4(bbase + SWZ(n * 128 + kb), t);
          bh[2 * p][0] = t[0]; bh[2 * p][1] = t[1];
          bh[2 * p + 1][0] = t[2]; bh[2 * p + 1][1] = t[3];
        }
#pragma unroll
        for (int mi = 0; mi < 2; mi++)
#pragma unroll
          for (int ni = 0; ni < 16; ni++)
            mma16816(acc[mi][ni], ah[mi], bh[ni]);
      }
    }
  }

  // ---- extract feat (chunks 4,5 live in stages 1,2) ----
  const int frow = tid >> 2;          // 0..63
  const int fc0 = (tid & 3) * 32;     // col base
  float fv[32];
#pragma unroll
  for (int c = 0; c < 32; c++) {
    int col = fc0 + c;
    int stg = 1 + (col >> 6);
    fv[c] = h2f(*(h16*)(smem + stg * GSG + G_A + SWZ(frow * 128 + (col & 63) * 2)));
  }
  __syncthreads();

  // ---- stash gate accumulators to smem sG[4][64][128] f32 ----
  float* sG = (float*)smem;
  const int gp = lid >> 2, tg = lid & 3;
#pragma unroll
  for (int mi = 0; mi < 2; mi++)
#pragma unroll
    for (int ni = 0; ni < 16; ni++) {
      int r = wm0 + mi * 16 + gp;
      int c = ni * 8 + tg * 2;
      sG[gate * 8192 + r * 128 + c] = acc[mi][ni][0];
      sG[gate * 8192 + r * 128 + c + 1] = acc[mi][ni][1];
      sG[gate * 8192 + (r + 8) * 128 + c] = acc[mi][ni][2];
      sG[gate * 8192 + (r + 8) * 128 + c + 1] = acc[mi][ni][3];
    }
  __syncthreads();

  // ---- GRU elementwise -> HNh (+ f32 last-node rows) ----
  const bool lastrow = ((m0 + frow) & 31) == 31;
  const int gidx = (m0 + frow) >> 5;
  __align__(16) h16 oh[32];
#pragma unroll
  for (int c = 0; c < 32; c++) {
    int col = fc0 + c;
    float rs = sG[frow * 128 + col] + sbias[col];
    float zs = sG[8192 + frow * 128 + col] + sbias[128 + col];
    float is = sG[2 * 8192 + frow * 128 + col] + sbias[256 + col];
    float hs = sG[3 * 8192 + frow * 128 + col] + sbias[384 + col];
    float r_ = sigf(rs), z_ = sigf(zs);
    float ng = tanh_fast(is + r_ * hs);
    float hn = (1.f - z_) * ng + z_ * fv[c];
    oh[c] = __float2half_rn(hn);
    if (lastrow) g_HNlast[(size_t)gidx * 128 + col] = hn;
  }
  {
    size_t o = (size_t)(m0 + frow) * 128 + fc0;
    int4* dh = (int4*)&g_HNh[o];
#pragma unroll
    for (int q = 0; q < 4; q++) dh[q] = ((int4*)oh)[q];
  }
}

// ================= U GEMM + attention + readout fused =================
__global__ void __launch_bounds__(128, 2) k_alpha(const float* __restrict__ cnt,
                                                  const float* __restrict__ we,
                                                  float* __restrict__ out) {
  extern __shared__ __align__(1024) char smem[];
  const uint32_t sb = smem_to_u32(smem);
  const int tid = threadIdx.x;
  const int lid = tid & 31, wid = tid >> 5;
  const int m0 = blockIdx.x * 128;
  const int g0 = m0 >> 5;
  const int wm0 = (wid & 1) * 64, wn0 = (wid >> 1) * 64;

  float* sFV = (float*)(smem + 2 * SG);   // [4][128]
  float* swe = sFV + 512;
  float* scnt = swe + 128;
  float* sPart = scnt + 128;              // [2][128]
  float* sAl = sPart + 256;               // [128]

  for (int i = tid; i < 512; i += 128)
    sFV[i] = g_FV[(size_t)(g0 + (i >> 7)) * 128 + (i & 127)];
  if (tid < 128) { swe[tid] = we[tid]; scnt[tid] = cnt[m0 + tid]; }

  auto issue = [&](int kc, int s) {
    uint32_t base = sb + s * SG;
#pragma unroll
    for (int i = 0; i < 8; i++) {
      int u = tid + 128 * i;
      int r = u >> 3, seg = u & 7;
      uint32_t d = SWZ(r * 128 + seg * 16);
      cp16(base + T_A + d, g_HNh + (size_t)(m0 + r) * 128 + kc + seg * 8);
      cp16(base + T_B + d, g_Wu + (size_t)r * 128 + kc + seg * 8);
    }
    CP_COMMIT();
  };

  float acc[4][8][4];
#pragma unroll
  for (int mi = 0; mi < 4; mi++)
#pragma unroll
    for (int ni = 0; ni < 8; ni++)
#pragma unroll
      for (int q = 0; q < 4; q++) acc[mi][ni][q] = 0.f;

  issue(0, 0);
  issue(64, 1);
  for (int c = 0; c < 2; c++) {
    if (c == 0) CP_WAIT(1); else CP_WAIT(0);
    __syncthreads();
    const uint32_t st = sb + c * SG;
    const int j = lid >> 3, rr = lid & 7;
#pragma unroll
    for (int kk = 0; kk < 4; kk++) {
      uint32_t ah[4][4], bh[8][2];
#pragma unroll
      for (int mi = 0; mi < 4; mi++) {
        int row = wm0 + mi * 16 + (j & 1) * 8 + rr;
        int kb = kk * 32 + (j >> 1) * 16;
        ldsm_x4(st + T_A + SWZ(row * 128 + kb), ah[mi]);
      }
#pragma unroll
      for (int p = 0; p < 4; p++) {
        int n = wn0 + p * 16 + (j >> 1) * 8 + rr;
        int kb = kk * 32 + (j & 1) * 16;
        uint32_t t[4];
        ldsm_x4(st + T_B + SWZ(n * 128 + kb), t);
        bh[2 * p][0] = t[0]; bh[2 * p][1] = t[1];
        bh[2 * p + 1][0] = t[2]; bh[2 * p + 1][1] = t[3];
      }
#pragma unroll
      for (int mi = 0; mi < 4; mi++)
#pragma unroll
        for (int ni = 0; ni < 8; ni++)
          mma16816(acc[mi][ni], ah[mi], bh[ni]);
    }
    __syncthreads();
  }

  // attention: e[row] = sum_j we[j]*sig(U[row][j] + FV[g][j])
  const int gp = lid >> 2, tg = lid & 3;
#pragma unroll
  for (int mi = 0; mi < 4; mi++) {
    int base = wm0 + mi * 16;
    int gl = base >> 5;
    float p0 = 0.f, p1 = 0.f;
#pragma unroll
    for (int ni = 0; ni < 8; ni++) {
      int jx = wn0 + ni * 8 + tg * 2;
      float fv0 = sFV[gl * 128 + jx], fv1 = sFV[gl * 128 + jx + 1];
      float w0 = swe[jx], w1 = swe[jx + 1];
      p0 += w0 * sigf(acc[mi][ni][0] + fv0) + w1 * sigf(acc[mi][ni][1] + fv1);
      p1 += w0 * sigf(acc[mi][ni][2] + fv0) + w1 * sigf(acc[mi][ni][3] + fv1);
    }
    p0 += __shfl_xor_sync(0xffffffffu, p0, 1);
    p0 += __shfl_xor_sync(0xffffffffu, p0, 2);
    p1 += __shfl_xor_sync(0xffffffffu, p1, 1);
    p1 += __shfl_xor_sync(0xffffffffu, p1, 2);
    if (tg == 0) {
      sPart[(wn0 >> 6) * 128 + base + gp] = p0;
      sPart[(wn0 >> 6) * 128 + base + gp + 8] = p1;
    }
  }
  __syncthreads();
  if (tid < 128)
    sAl[tid] = (sPart[tid] + sPart[128 + tid]) * scnt[tid];
  __syncthreads();

  // readout: hn read from HNh tiles still resident in both stages
#pragma unroll
  for (int v = 0; v < 4; v++) {
    int idx = tid + v * 128;
    int gl = idx >> 7, jx = idx & 127;
    int stg = jx >> 6, cidx = jx & 63;
    float accg = 0.f;
#pragma unroll
    for (int n = 0; n < 32; n++) {
      int rowl = gl * 32 + n;
      float hn = h2f(*(h16*)(smem + stg * SG + T_A + SWZ(rowl * 128 + cidx * 2)));
      accg += hn * sAl[rowl];
    }
    out[(size_t)(g0 + gl) * 256 + jx] = accg;
    out[(size_t)(g0 + gl) * 256 + 128 + jx] = g_HNlast[(size_t)(g0 + gl) * 128 + jx];
  }
}

// ================= host =================
extern "C" void kernel_launch(void* const* d_in, const int* in_sizes, int n_in,
                              void* d_out, int out_size) {
  const float* feat = (const float*)d_in[0];
  const float* cnt  = (const float*)d_in[1];
  const float* W_in = (const float*)d_in[2];
  const float* b_in = (const float*)d_in[3];
  const float* W_og = (const float*)d_in[4];
  const float* b_og = (const float*)d_in[5];
  const float* W_ih = (const float*)d_in[6];
  const float* b_ih = (const float*)d_in[7];
  const float* W_hh = (const float*)d_in[8];
  const float* b_hh = (const float*)d_in[9];
  const float* W_u  = (const float*)d_in[10];
  const float* W_v  = (const float*)d_in[11];
  const float* b_v  = (const float*)d_in[12];
  const float* w_e  = (const float*)d_in[13];
  const int*   src  = (const int*)d_in[14];
  const int*   dst  = (const int*)d_in[15];
  float* out = (float*)d_out;

  h16 *featH, *HNh, *Wio, *Wv;
  float *FV, *biasY;
  cudaGetSymbolAddress((void**)&featH, g_featH);
  cudaGetSymbolAddress((void**)&HNh, g_HNh);
  cudaGetSymbolAddress((void**)&FV, g_FV);
  cudaGetSymbolAddress((void**)&Wio, g_Wio);
  cudaGetSymbolAddress((void**)&Wv, g_Wv);
  cudaGetSymbolAddress((void**)&biasY, g_biasY);

  const int SM_PLAIN = 2 * SG;                  // 65536
  const int SM_AGG = 84992;                     // sC + adj + rdeg
  const int SM_GATES = 3 * GSG + 2048;          // 174080
  const int SM_ALPHA = 2 * SG + 4608;           // 70144
  static bool attr_done = false;
  if (!attr_done) {
    cudaFuncSetAttribute(k_mma<EPI_PLAIN>, cudaFuncAttributeMaxDynamicSharedMemorySize, SM_PLAIN);
    cudaFuncSetAttribute(k_mma<EPI_AGG>, cudaFuncAttributeMaxDynamicSharedMemorySize, SM_AGG);
    cudaFuncSetAttribute(k_gates, cudaFuncAttributeMaxDynamicSharedMemorySize, SM_GATES);
    cudaFuncSetAttribute(k_alpha, cudaFuncAttributeMaxDynamicSharedMemorySize, SM_ALPHA);
    attr_done = true;
  }

  k_zero_adj<<<512, 256>>>();
  k_build_adj<<<NEDGE / 256, 256>>>(src, dst);
  k_pack<<<256, 256>>>(W_in, W_og, W_ih, W_hh, W_u, W_v, b_in, b_og, b_ih, b_hh);
  k_conv_feat<<<2048, 256>>>(feat);

  // Y = feat @ [W_in;W_og]^T + biasY -> fused per-graph aggregation -> AggH
  k_mma<EPI_AGG><<<dim3(NNODE / 128, 2), 128, SM_AGG>>>(
      featH, 128, Wio, 128, biasY, nullptr, 0);

  // gates + fused GRU -> HNh (+ f32 last rows)
  k_gates<<<NNODE / 64, 256, SM_GATES>>>();

  // FV = hn[last] @ W_v^T + b_v
  k_mma<EPI_PLAIN><<<dim3(NGRAPH / 128, 1), 128, SM_PLAIN>>>(
      HNh + 31 * 128, 4096, Wv, 128, b_v, FV, 128);

  // U GEMM + attention + readout -> out
  k_alpha<<<NNODE / 128, 128, SM_ALPHA>>>(cnt, w_e, out);
}